// round 3
// baseline (speedup 1.0000x reference)
#include <cuda_runtime.h>
#include <cuda_fp16.h>

#define N_NODES 50000
#define N_EDGES 1600000

// ---- scratch (static __device__, no allocs) ----
__device__ int g_deg[N_NODES];
__device__ int g_off[N_NODES + 1];
__device__ int g_cur[N_NODES];
__device__ int g_csr[N_EDGES];
__device__ __half g_hA[N_NODES * 64];   // pre-agg features, fp16 (agg gathers these)
__device__ float g_bufB[N_NODES * 64];  // post-agg features, fp32
__device__ float g_h3[N_NODES * 8];
__device__ float g_wt1[64 * 64];
__device__ float g_wt2[64 * 64];
__device__ float g_wt3[64 * 8];

// ------------- zero degree counters + weight transposes, one kernel -------------

__global__ void k_zero_prep(const float* __restrict__ W1, const float* __restrict__ W2,
                            const float* __restrict__ W3) {
    int i = blockIdx.x * blockDim.x + threadIdx.x;
    if (i < N_NODES) g_deg[i] = 0;
    if (blockIdx.x == 0) {
        for (int t = threadIdx.x; t < 64 * 64; t += blockDim.x) {
            int j = t >> 6, k = t & 63;
            g_wt1[k * 64 + j] = W1[t];
            g_wt2[k * 64 + j] = W2[t];
        }
        for (int t = threadIdx.x; t < 64 * 8; t += blockDim.x) {
            int k = t >> 3, j = t & 7;
            g_wt3[t] = (j < 7) ? W3[j * 64 + k] : 0.f;
        }
    }
}

// ---------------- histogram of dst degrees ----------------

__global__ void k_hist(const int* __restrict__ ei) {
    int i = blockIdx.x * blockDim.x + threadIdx.x;
    if (i < N_EDGES) {
        int d = ei[N_EDGES + i];
        if ((unsigned)d < N_NODES) atomicAdd(&g_deg[d], 1);
    }
}

// -------- single-block exclusive scan over 50K degrees (49 tiles of 1024) --------

__global__ __launch_bounds__(1024) void k_scan() {
    __shared__ int wsum[32];
    __shared__ int carry;
    int t = threadIdx.x, lane = t & 31, wid = t >> 5;
    if (t == 0) carry = 0;
    __syncthreads();
    for (int base = 0; base < N_NODES; base += 1024) {
        int i = base + t;
        int v = (i < N_NODES) ? g_deg[i] : 0;
        int incl = v;
        #pragma unroll
        for (int o = 1; o < 32; o <<= 1) {
            int x = __shfl_up_sync(~0u, incl, o);
            if (lane >= o) incl += x;
        }
        if (lane == 31) wsum[wid] = incl;
        __syncthreads();
        if (wid == 0) {
            int w = wsum[lane];
            int wi = w;
            #pragma unroll
            for (int o = 1; o < 32; o <<= 1) {
                int x = __shfl_up_sync(~0u, wi, o);
                if (lane >= o) wi += x;
            }
            wsum[lane] = wi - w;  // exclusive warp base
        }
        __syncthreads();
        int ex = carry + wsum[wid] + incl - v;
        if (i < N_NODES) { g_off[i] = ex; g_cur[i] = ex; }
        __syncthreads();               // everyone done reading carry
        if (t == 1023) carry = ex + v; // block-inclusive total
        __syncthreads();
    }
    if (t == 0) g_off[N_NODES] = carry;
}

// ---------------- scatter edges into CSC ----------------

__global__ void k_scatter(const int* __restrict__ ei) {
    int i = blockIdx.x * blockDim.x + threadIdx.x;
    if (i < N_EDGES) {
        int s = ei[i];
        int d = ei[N_EDGES + i];
        if ((unsigned)d < N_NODES) {
            int pos = atomicAdd(&g_cur[d], 1);
            g_csr[pos] = ((unsigned)s < N_NODES) ? s : 0;
        }
    }
}

// ------- GEMM 64x64 -> fp16 output: out[n][j] = sum_k in[n][k] * W[j][k] -------
// 64 nodes per block, 256 threads, 4x4 micro-tile per thread.

__global__ __launch_bounds__(256) void k_gemm64h(const float* __restrict__ in,
                                                 const float* __restrict__ wt,
                                                 __half* __restrict__ out) {
    __shared__ __align__(16) float sW[64 * 64];
    __shared__ float sX[64 * 65];
    int n0 = blockIdx.x * 64;
    for (int i = threadIdx.x; i < 4096; i += 256) sW[i] = wt[i];
    for (int i = threadIdx.x; i < 4096; i += 256) {
        int n = i >> 6, k = i & 63;
        sX[n * 65 + k] = (n0 + n < N_NODES) ? in[(n0 + n) * 64 + k] : 0.f;
    }
    __syncthreads();
    int tx = threadIdx.x & 15, ty = threadIdx.x >> 4;
    float acc[4][4] = {};
    #pragma unroll 8
    for (int k = 0; k < 64; k++) {
        float4 w = *(const float4*)&sW[k * 64 + tx * 4];
        #pragma unroll
        for (int i = 0; i < 4; i++) {
            float xv = sX[(ty * 4 + i) * 65 + k];
            acc[i][0] += xv * w.x;
            acc[i][1] += xv * w.y;
            acc[i][2] += xv * w.z;
            acc[i][3] += xv * w.w;
        }
    }
    #pragma unroll
    for (int i = 0; i < 4; i++) {
        int n = n0 + ty * 4 + i;
        if (n < N_NODES) {
            __half2 h0 = __floats2half2_rn(acc[i][0], acc[i][1]);
            __half2 h1 = __floats2half2_rn(acc[i][2], acc[i][3]);
            uint2 pk = {*(unsigned*)&h0, *(unsigned*)&h1};
            *(uint2*)&out[n * 64 + tx * 4] = pk;
        }
    }
}

// ---- aggregation 64ch from fp16: warp per dst node, fp32 accum, no atomics ----

template <bool RELU>
__global__ __launch_bounds__(256) void k_agg64h(const __half2* __restrict__ h2,
                                                const float* __restrict__ bias,
                                                float* __restrict__ out) {
    int n = (blockIdx.x * blockDim.x + threadIdx.x) >> 5;
    int lane = threadIdx.x & 31;
    if (n >= N_NODES) return;
    int beg = g_off[n], end = g_off[n + 1];
    float ax = 0.f, ay = 0.f;
    int e = beg;
    for (; e + 4 <= end; e += 4) {  // unroll-4 for MLP
        int s0 = g_csr[e], s1 = g_csr[e + 1], s2 = g_csr[e + 2], s3 = g_csr[e + 3];
        float2 v0 = __half22float2(h2[s0 * 32 + lane]);
        float2 v1 = __half22float2(h2[s1 * 32 + lane]);
        float2 v2 = __half22float2(h2[s2 * 32 + lane]);
        float2 v3 = __half22float2(h2[s3 * 32 + lane]);
        ax += (v0.x + v1.x) + (v2.x + v3.x);
        ay += (v0.y + v1.y) + (v2.y + v3.y);
    }
    for (; e < end; e++) {
        float2 v = __half22float2(h2[g_csr[e] * 32 + lane]);
        ax += v.x; ay += v.y;
    }
    float2 b = ((const float2*)bias)[lane];
    float rx = ax + b.x, ry = ay + b.y;
    if (RELU) { rx = fmaxf(rx, 0.f); ry = fmaxf(ry, 0.f); }
    ((float2*)out)[n * 32 + lane] = make_float2(rx, ry);
}

// ---------------- layer 3 projection: 64 -> 7 (padded to 8), fp32 ----------------

__global__ __launch_bounds__(128) void k_gemm7(const float* __restrict__ in) {
    __shared__ float sX[128 * 65];
    __shared__ float sW[64 * 8];
    int n0 = blockIdx.x * 128;
    for (int i = threadIdx.x; i < 512; i += 128) sW[i] = g_wt3[i];
    for (int i = threadIdx.x; i < 8192; i += 128) {
        int n = i >> 6, k = i & 63;
        sX[n * 65 + k] = (n0 + n < N_NODES) ? in[(n0 + n) * 64 + k] : 0.f;
    }
    __syncthreads();
    int n = n0 + threadIdx.x;
    float a[7] = {};
    #pragma unroll 8
    for (int k = 0; k < 64; k++) {
        float xv = sX[threadIdx.x * 65 + k];
        #pragma unroll
        for (int j = 0; j < 7; j++) a[j] += xv * sW[k * 8 + j];
    }
    if (n < N_NODES) {
        float4 r0 = {a[0], a[1], a[2], a[3]};
        float4 r1 = {a[4], a[5], a[6], 0.f};
        *(float4*)&g_h3[n * 8] = r0;
        *(float4*)&g_h3[n * 8 + 4] = r1;
    }
}

// -------- aggregation 7ch + bias + log_softmax, thread per node, fp32 --------

__global__ __launch_bounds__(256) void k_agg7(const float* __restrict__ b3,
                                              float* __restrict__ out) {
    int n = blockIdx.x * blockDim.x + threadIdx.x;
    if (n >= N_NODES) return;
    int beg = g_off[n], end = g_off[n + 1];
    float a[7] = {};
    int e = beg;
    for (; e + 2 <= end; e += 2) {
        int s0 = g_csr[e], s1 = g_csr[e + 1];
        float4 u0 = *(const float4*)&g_h3[s0 * 8];
        float4 v0 = *(const float4*)&g_h3[s0 * 8 + 4];
        float4 u1 = *(const float4*)&g_h3[s1 * 8];
        float4 v1 = *(const float4*)&g_h3[s1 * 8 + 4];
        a[0] += u0.x + u1.x; a[1] += u0.y + u1.y; a[2] += u0.z + u1.z;
        a[3] += u0.w + u1.w; a[4] += v0.x + v1.x; a[5] += v0.y + v1.y;
        a[6] += v0.z + v1.z;
    }
    for (; e < end; e++) {
        int s = g_csr[e];
        float4 u = *(const float4*)&g_h3[s * 8];
        float4 v = *(const float4*)&g_h3[s * 8 + 4];
        a[0] += u.x; a[1] += u.y; a[2] += u.z; a[3] += u.w;
        a[4] += v.x; a[5] += v.y; a[6] += v.z;
    }
    #pragma unroll
    for (int j = 0; j < 7; j++) a[j] += b3[j];
    float m = a[0];
    #pragma unroll
    for (int j = 1; j < 7; j++) m = fmaxf(m, a[j]);
    float se = 0.f;
    #pragma unroll
    for (int j = 0; j < 7; j++) se += __expf(a[j] - m);
    float ls = __logf(se);
    #pragma unroll
    for (int j = 0; j < 7; j++) out[n * 7 + j] = a[j] - m - ls;
}

// ---------------- launch ----------------

extern "C" void kernel_launch(void* const* d_in, const int* in_sizes, int n_in,
                              void* d_out, int out_size) {
    const float* x = (const float*)d_in[0];
    const int* ei = (const int*)d_in[1];   // edge_index materializes as int32
    const float* W1 = (const float*)d_in[2];
    const float* b1 = (const float*)d_in[3];
    const float* W2 = (const float*)d_in[4];
    const float* b2 = (const float*)d_in[5];
    const float* W3 = (const float*)d_in[6];
    const float* b3 = (const float*)d_in[7];
    float* out = (float*)d_out;

    void *pA, *pB, *pw1, *pw2;
    cudaGetSymbolAddress(&pA, g_hA);
    cudaGetSymbolAddress(&pB, g_bufB);
    cudaGetSymbolAddress(&pw1, g_wt1);
    cudaGetSymbolAddress(&pw2, g_wt2);

    // CSC build (counting sort by dst)
    k_zero_prep<<<(N_NODES + 255) / 256, 256>>>(W1, W2, W3);
    k_hist<<<(N_EDGES + 255) / 256, 256>>>(ei);
    k_scan<<<1, 1024>>>();
    k_scatter<<<(N_EDGES + 255) / 256, 256>>>(ei);

    // layer 1
    k_gemm64h<<<(N_NODES + 63) / 64, 256>>>(x, (const float*)pw1, (__half*)pA);
    k_agg64h<true><<<(N_NODES * 32 + 255) / 256, 256>>>((const __half2*)pA, b1, (float*)pB);
    // layer 2
    k_gemm64h<<<(N_NODES + 63) / 64, 256>>>((const float*)pB, (const float*)pw2, (__half*)pA);
    k_agg64h<true><<<(N_NODES * 32 + 255) / 256, 256>>>((const __half2*)pA, b2, (float*)pB);
    // layer 3 + log_softmax
    k_gemm7<<<(N_NODES + 127) / 128, 128>>>((const float*)pB);
    k_agg7<<<(N_NODES + 255) / 256, 256>>>(b3, out);
}

// round 4
// speedup vs baseline: 1.1513x; 1.1513x over previous
#include <cuda_runtime.h>
#include <cuda_fp16.h>

#define N_NODES 50000
#define N_EDGES 1600000
#define NB_SCAN ((N_NODES + 1023) / 1024)  // 49

// ---- scratch (static __device__, no allocs) ----
__device__ int g_deg[N_NODES];
__device__ int g_off[N_NODES + 1];
__device__ int g_cur[N_NODES];
__device__ int g_bsum[NB_SCAN];
__device__ int g_csr[N_EDGES];
__device__ __half g_hA[N_NODES * 64];   // pre-agg features, fp16 (agg gathers these)
__device__ float g_bufB[N_NODES * 64];  // post-agg features, fp32
__device__ float g_h3[N_NODES * 8];
__device__ float g_wt1[64 * 64];
__device__ float g_wt2[64 * 64];
__device__ float g_wt3[64 * 8];

// ------------- zero degree counters + weight transposes, one kernel -------------

__global__ void k_zero_prep(const float* __restrict__ W1, const float* __restrict__ W2,
                            const float* __restrict__ W3) {
    int i = blockIdx.x * blockDim.x + threadIdx.x;
    if (i < N_NODES) g_deg[i] = 0;
    if (blockIdx.x == 0) {
        for (int t = threadIdx.x; t < 64 * 64; t += blockDim.x) {
            int j = t >> 6, k = t & 63;
            g_wt1[k * 64 + j] = W1[t];
            g_wt2[k * 64 + j] = W2[t];
        }
        for (int t = threadIdx.x; t < 64 * 8; t += blockDim.x) {
            int k = t >> 3, j = t & 7;
            g_wt3[t] = (j < 7) ? W3[j * 64 + k] : 0.f;
        }
    }
}

// ---------------- histogram of dst degrees, 4 edges/thread ----------------

__global__ void k_hist(const int* __restrict__ ei) {
    int i = (blockIdx.x * blockDim.x + threadIdx.x) * 4;
    if (i < N_EDGES) {
        int4 d4 = *(const int4*)&ei[N_EDGES + i];
        if ((unsigned)d4.x < N_NODES) atomicAdd(&g_deg[d4.x], 1);
        if ((unsigned)d4.y < N_NODES) atomicAdd(&g_deg[d4.y], 1);
        if ((unsigned)d4.z < N_NODES) atomicAdd(&g_deg[d4.z], 1);
        if ((unsigned)d4.w < N_NODES) atomicAdd(&g_deg[d4.w], 1);
    }
}

// -------- parallel scan: per-block sums -> scan of partials -> offsets --------

__global__ void k_part() {  // NB_SCAN blocks x 1024: per-block sums
    __shared__ int sm[32];
    int i = blockIdx.x * 1024 + threadIdx.x;
    int v = (i < N_NODES) ? g_deg[i] : 0;
    #pragma unroll
    for (int o = 16; o > 0; o >>= 1) v += __shfl_down_sync(~0u, v, o);
    if ((threadIdx.x & 31) == 0) sm[threadIdx.x >> 5] = v;
    __syncthreads();
    if (threadIdx.x < 32) {
        int w = sm[threadIdx.x];
        #pragma unroll
        for (int o = 16; o > 0; o >>= 1) w += __shfl_down_sync(~0u, w, o);
        if (threadIdx.x == 0) g_bsum[blockIdx.x] = w;
    }
}

__global__ void k_scanpart() {  // 1 block, 64 threads: exclusive scan of partials
    __shared__ int s[64];
    int t = threadIdx.x;
    int v = (t < NB_SCAN) ? g_bsum[t] : 0;
    s[t] = v;
    __syncthreads();
    for (int d = 1; d < 64; d <<= 1) {
        int x = (t >= d) ? s[t - d] : 0;
        __syncthreads();
        s[t] += x;
        __syncthreads();
    }
    if (t < NB_SCAN) g_bsum[t] = s[t] - v;      // exclusive block base
    if (t == 0) g_off[N_NODES] = s[63];         // total
}

__global__ void k_offsets() {  // NB_SCAN blocks x 1024: final exclusive offsets
    __shared__ int wpart[32];
    int i = blockIdx.x * 1024 + threadIdx.x;
    int v = (i < N_NODES) ? g_deg[i] : 0;
    int lane = threadIdx.x & 31, wid = threadIdx.x >> 5;
    int incl = v;
    #pragma unroll
    for (int o = 1; o < 32; o <<= 1) {
        int x = __shfl_up_sync(~0u, incl, o);
        if (lane >= o) incl += x;
    }
    if (lane == 31) wpart[wid] = incl;
    __syncthreads();
    if (wid == 0) {
        int w = wpart[lane];
        int wi = w;
        #pragma unroll
        for (int o = 1; o < 32; o <<= 1) {
            int x = __shfl_up_sync(~0u, wi, o);
            if (lane >= o) wi += x;
        }
        wpart[lane] = wi - w;  // exclusive warp base
    }
    __syncthreads();
    if (i < N_NODES) {
        int ex = g_bsum[blockIdx.x] + wpart[wid] + incl - v;
        g_off[i] = ex;
        g_cur[i] = ex;
    }
}

// ---------------- scatter edges into CSC, 4 edges/thread ----------------

__global__ void k_scatter(const int* __restrict__ ei) {
    int i = (blockIdx.x * blockDim.x + threadIdx.x) * 4;
    if (i < N_EDGES) {
        int4 s4 = *(const int4*)&ei[i];
        int4 d4 = *(const int4*)&ei[N_EDGES + i];
        // 4 independent atomics in flight (MLP=4 hides ATOMG latency)
        int p0 = ((unsigned)d4.x < N_NODES) ? atomicAdd(&g_cur[d4.x], 1) : -1;
        int p1 = ((unsigned)d4.y < N_NODES) ? atomicAdd(&g_cur[d4.y], 1) : -1;
        int p2 = ((unsigned)d4.z < N_NODES) ? atomicAdd(&g_cur[d4.z], 1) : -1;
        int p3 = ((unsigned)d4.w < N_NODES) ? atomicAdd(&g_cur[d4.w], 1) : -1;
        if (p0 >= 0) g_csr[p0] = ((unsigned)s4.x < N_NODES) ? s4.x : 0;
        if (p1 >= 0) g_csr[p1] = ((unsigned)s4.y < N_NODES) ? s4.y : 0;
        if (p2 >= 0) g_csr[p2] = ((unsigned)s4.z < N_NODES) ? s4.z : 0;
        if (p3 >= 0) g_csr[p3] = ((unsigned)s4.w < N_NODES) ? s4.w : 0;
    }
}

// ------- GEMM 64x64 -> fp16 output: out[n][j] = sum_k in[n][k] * W[j][k] -------

__global__ __launch_bounds__(256) void k_gemm64h(const float* __restrict__ in,
                                                 const float* __restrict__ wt,
                                                 __half* __restrict__ out) {
    __shared__ __align__(16) float sW[64 * 64];
    __shared__ float sX[64 * 65];
    int n0 = blockIdx.x * 64;
    for (int i = threadIdx.x; i < 4096; i += 256) sW[i] = wt[i];
    for (int i = threadIdx.x; i < 4096; i += 256) {
        int n = i >> 6, k = i & 63;
        sX[n * 65 + k] = (n0 + n < N_NODES) ? in[(n0 + n) * 64 + k] : 0.f;
    }
    __syncthreads();
    int tx = threadIdx.x & 15, ty = threadIdx.x >> 4;
    float acc[4][4] = {};
    #pragma unroll 8
    for (int k = 0; k < 64; k++) {
        float4 w = *(const float4*)&sW[k * 64 + tx * 4];
        #pragma unroll
        for (int i = 0; i < 4; i++) {
            float xv = sX[(ty * 4 + i) * 65 + k];
            acc[i][0] += xv * w.x;
            acc[i][1] += xv * w.y;
            acc[i][2] += xv * w.z;
            acc[i][3] += xv * w.w;
        }
    }
    #pragma unroll
    for (int i = 0; i < 4; i++) {
        int n = n0 + ty * 4 + i;
        if (n < N_NODES) {
            __half2 h0 = __floats2half2_rn(acc[i][0], acc[i][1]);
            __half2 h1 = __floats2half2_rn(acc[i][2], acc[i][3]);
            uint2 pk = {*(unsigned*)&h0, *(unsigned*)&h1};
            *(uint2*)&out[n * 64 + tx * 4] = pk;
        }
    }
}

// ---- aggregation 64ch from fp16: warp per dst node, fp32 accum, no atomics ----

template <bool RELU>
__global__ __launch_bounds__(256) void k_agg64h(const __half2* __restrict__ h2,
                                                const float* __restrict__ bias,
                                                float* __restrict__ out) {
    int n = (blockIdx.x * blockDim.x + threadIdx.x) >> 5;
    int lane = threadIdx.x & 31;
    if (n >= N_NODES) return;
    int beg = g_off[n], end = g_off[n + 1];
    float ax = 0.f, ay = 0.f;
    int e = beg;
    for (; e + 4 <= end; e += 4) {  // unroll-4 for MLP
        int s0 = g_csr[e], s1 = g_csr[e + 1], s2 = g_csr[e + 2], s3 = g_csr[e + 3];
        float2 v0 = __half22float2(h2[s0 * 32 + lane]);
        float2 v1 = __half22float2(h2[s1 * 32 + lane]);
        float2 v2 = __half22float2(h2[s2 * 32 + lane]);
        float2 v3 = __half22float2(h2[s3 * 32 + lane]);
        ax += (v0.x + v1.x) + (v2.x + v3.x);
        ay += (v0.y + v1.y) + (v2.y + v3.y);
    }
    for (; e < end; e++) {
        float2 v = __half22float2(h2[g_csr[e] * 32 + lane]);
        ax += v.x; ay += v.y;
    }
    float2 b = ((const float2*)bias)[lane];
    float rx = ax + b.x, ry = ay + b.y;
    if (RELU) { rx = fmaxf(rx, 0.f); ry = fmaxf(ry, 0.f); }
    ((float2*)out)[n * 32 + lane] = make_float2(rx, ry);
}

// ---------------- layer 3 projection: 64 -> 7 (padded to 8), fp32 ----------------

__global__ __launch_bounds__(128) void k_gemm7(const float* __restrict__ in) {
    __shared__ float sX[128 * 65];
    __shared__ float sW[64 * 8];
    int n0 = blockIdx.x * 128;
    for (int i = threadIdx.x; i < 512; i += 128) sW[i] = g_wt3[i];
    for (int i = threadIdx.x; i < 8192; i += 128) {
        int n = i >> 6, k = i & 63;
        sX[n * 65 + k] = (n0 + n < N_NODES) ? in[(n0 + n) * 64 + k] : 0.f;
    }
    __syncthreads();
    int n = n0 + threadIdx.x;
    float a[7] = {};
    #pragma unroll 8
    for (int k = 0; k < 64; k++) {
        float xv = sX[threadIdx.x * 65 + k];
        #pragma unroll
        for (int j = 0; j < 7; j++) a[j] += xv * sW[k * 8 + j];
    }
    if (n < N_NODES) {
        float4 r0 = {a[0], a[1], a[2], a[3]};
        float4 r1 = {a[4], a[5], a[6], 0.f};
        *(float4*)&g_h3[n * 8] = r0;
        *(float4*)&g_h3[n * 8 + 4] = r1;
    }
}

// -------- aggregation 7ch + bias + log_softmax, thread per node, fp32 --------

__global__ __launch_bounds__(256) void k_agg7(const float* __restrict__ b3,
                                              float* __restrict__ out) {
    int n = blockIdx.x * blockDim.x + threadIdx.x;
    if (n >= N_NODES) return;
    int beg = g_off[n], end = g_off[n + 1];
    float a[7] = {};
    int e = beg;
    for (; e + 2 <= end; e += 2) {
        int s0 = g_csr[e], s1 = g_csr[e + 1];
        float4 u0 = *(const float4*)&g_h3[s0 * 8];
        float4 v0 = *(const float4*)&g_h3[s0 * 8 + 4];
        float4 u1 = *(const float4*)&g_h3[s1 * 8];
        float4 v1 = *(const float4*)&g_h3[s1 * 8 + 4];
        a[0] += u0.x + u1.x; a[1] += u0.y + u1.y; a[2] += u0.z + u1.z;
        a[3] += u0.w + u1.w; a[4] += v0.x + v1.x; a[5] += v0.y + v1.y;
        a[6] += v0.z + v1.z;
    }
    for (; e < end; e++) {
        int s = g_csr[e];
        float4 u = *(const float4*)&g_h3[s * 8];
        float4 v = *(const float4*)&g_h3[s * 8 + 4];
        a[0] += u.x; a[1] += u.y; a[2] += u.z; a[3] += u.w;
        a[4] += v.x; a[5] += v.y; a[6] += v.z;
    }
    #pragma unroll
    for (int j = 0; j < 7; j++) a[j] += b3[j];
    float m = a[0];
    #pragma unroll
    for (int j = 1; j < 7; j++) m = fmaxf(m, a[j]);
    float se = 0.f;
    #pragma unroll
    for (int j = 0; j < 7; j++) se += __expf(a[j] - m);
    float ls = __logf(se);
    #pragma unroll
    for (int j = 0; j < 7; j++) out[n * 7 + j] = a[j] - m - ls;
}

// ---------------- launch ----------------

extern "C" void kernel_launch(void* const* d_in, const int* in_sizes, int n_in,
                              void* d_out, int out_size) {
    const float* x = (const float*)d_in[0];
    const int* ei = (const int*)d_in[1];   // edge_index materializes as int32
    const float* W1 = (const float*)d_in[2];
    const float* b1 = (const float*)d_in[3];
    const float* W2 = (const float*)d_in[4];
    const float* b2 = (const float*)d_in[5];
    const float* W3 = (const float*)d_in[6];
    const float* b3 = (const float*)d_in[7];
    float* out = (float*)d_out;

    void *pA, *pB, *pw1, *pw2;
    cudaGetSymbolAddress(&pA, g_hA);
    cudaGetSymbolAddress(&pB, g_bufB);
    cudaGetSymbolAddress(&pw1, g_wt1);
    cudaGetSymbolAddress(&pw2, g_wt2);

    // CSC build (counting sort by dst)
    k_zero_prep<<<(N_NODES + 255) / 256, 256>>>(W1, W2, W3);
    k_hist<<<(N_EDGES / 4 + 255) / 256, 256>>>(ei);
    k_part<<<NB_SCAN, 1024>>>();
    k_scanpart<<<1, 64>>>();
    k_offsets<<<NB_SCAN, 1024>>>();
    k_scatter<<<(N_EDGES / 4 + 255) / 256, 256>>>(ei);

    // layer 1
    k_gemm64h<<<(N_NODES + 63) / 64, 256>>>(x, (const float*)pw1, (__half*)pA);
    k_agg64h<true><<<(N_NODES * 32 + 255) / 256, 256>>>((const __half2*)pA, b1, (float*)pB);
    // layer 2
    k_gemm64h<<<(N_NODES + 63) / 64, 256>>>((const float*)pB, (const float*)pw2, (__half*)pA);
    k_agg64h<true><<<(N_NODES * 32 + 255) / 256, 256>>>((const __half2*)pA, b2, (float*)pB);
    // layer 3 + log_softmax
    k_gemm7<<<(N_NODES + 127) / 128, 128>>>((const float*)pB);
    k_agg7<<<(N_NODES + 255) / 256, 256>>>(b3, out);
}

// round 5
// speedup vs baseline: 1.2899x; 1.1204x over previous
#include <cuda_runtime.h>
#include <cuda_fp16.h>

#define N_NODES 50000
#define N_EDGES 1600000
#define NB_SCAN ((N_NODES + 1023) / 1024)  // 49

// ---- scratch (static __device__, no allocs) ----
__device__ int g_deg[N_NODES];
__device__ int g_off[N_NODES + 1];
__device__ int g_cur[N_NODES];
__device__ int g_aggr[NB_SCAN];
__device__ int g_flagA[NB_SCAN];
__device__ int g_csr[N_EDGES];
__device__ __half g_hA[N_NODES * 64];    // pre-agg features, fp16
__device__ float g_bufB[N_NODES * 64];   // post-agg features, fp32
__device__ __half g_h3h[N_NODES * 8];    // layer-3 pre-agg, fp16 (7 used + pad)
__device__ float g_wt1[64 * 64];
__device__ float g_wt2[64 * 64];
__device__ float g_wt3[64 * 8];

// ---------------- zero degree counters + lookback flags ----------------

__global__ void k_zero() {
    int i = blockIdx.x * blockDim.x + threadIdx.x;
    if (i < N_NODES) g_deg[i] = 0;
    if (i < NB_SCAN) g_flagA[i] = 0;
}

// ---------------- weight transposes (Wt[k][j] = W[j][k]) ----------------

__global__ void k_prep_w(const float* __restrict__ W1, const float* __restrict__ W2,
                         const float* __restrict__ W3) {
    for (int t = threadIdx.x; t < 64 * 64; t += blockDim.x) {
        int j = t >> 6, k = t & 63;
        g_wt1[k * 64 + j] = W1[t];
        g_wt2[k * 64 + j] = W2[t];
    }
    for (int t = threadIdx.x; t < 64 * 8; t += blockDim.x) {
        int k = t >> 3, j = t & 7;
        g_wt3[t] = (j < 7) ? W3[j * 64 + k] : 0.f;
    }
}

// ---------------- histogram of dst degrees, 4 edges/thread ----------------

__global__ void k_hist(const int* __restrict__ ei) {
    int i = (blockIdx.x * blockDim.x + threadIdx.x) * 4;
    if (i < N_EDGES) {
        int4 d4 = *(const int4*)&ei[N_EDGES + i];
        if ((unsigned)d4.x < N_NODES) atomicAdd(&g_deg[d4.x], 1);
        if ((unsigned)d4.y < N_NODES) atomicAdd(&g_deg[d4.y], 1);
        if ((unsigned)d4.z < N_NODES) atomicAdd(&g_deg[d4.z], 1);
        if ((unsigned)d4.w < N_NODES) atomicAdd(&g_deg[d4.w], 1);
    }
}

// ------ single-kernel exclusive scan: 49 co-resident blocks + lookback ------

__global__ __launch_bounds__(1024) void k_scan2() {
    __shared__ int wsum[32];
    __shared__ int s_base;
    int b = blockIdx.x, t = threadIdx.x, lane = t & 31, wid = t >> 5;
    int i = b * 1024 + t;
    int v = (i < N_NODES) ? g_deg[i] : 0;
    int incl = v;
    #pragma unroll
    for (int o = 1; o < 32; o <<= 1) {
        int x = __shfl_up_sync(~0u, incl, o);
        if (lane >= o) incl += x;
    }
    if (lane == 31) wsum[wid] = incl;
    __syncthreads();
    if (wid == 0) {
        int w = wsum[lane];
        int wi = w;
        #pragma unroll
        for (int o = 1; o < 32; o <<= 1) {
            int x = __shfl_up_sync(~0u, wi, o);
            if (lane >= o) wi += x;
        }
        wsum[lane] = wi - w;  // exclusive warp base
        if (lane == 31) {     // publish block aggregate ASAP
            g_aggr[b] = wi;
            __threadfence();
            atomicExch(&g_flagA[b], 1);
        }
    }
    __syncthreads();
    // warp 0: sum aggregates of all predecessor blocks (warp-batched spin)
    if (wid == 0) {
        int run = 0;
        for (int base = 0; base < b; base += 32) {
            int j = base + lane;
            int a = 0;
            if (j < b) {
                while (atomicAdd(&g_flagA[j], 0) == 0) {}
                a = atomicAdd(&g_aggr[j], 0);
            }
            #pragma unroll
            for (int o = 16; o > 0; o >>= 1) a += __shfl_down_sync(~0u, a, o);
            run += __shfl_sync(~0u, a, 0);
        }
        if (lane == 0) s_base = run;
    }
    __syncthreads();
    int ex = s_base + wsum[wid] + incl - v;
    if (i < N_NODES) { g_off[i] = ex; g_cur[i] = ex; }
    if (b == NB_SCAN - 1 && t == 0) g_off[N_NODES] = s_base + g_aggr[b];
}

// ---------------- scatter edges into CSC, 4 edges/thread ----------------

__global__ void k_scatter(const int* __restrict__ ei) {
    int i = (blockIdx.x * blockDim.x + threadIdx.x) * 4;
    if (i < N_EDGES) {
        int4 s4 = *(const int4*)&ei[i];
        int4 d4 = *(const int4*)&ei[N_EDGES + i];
        int p0 = ((unsigned)d4.x < N_NODES) ? atomicAdd(&g_cur[d4.x], 1) : -1;
        int p1 = ((unsigned)d4.y < N_NODES) ? atomicAdd(&g_cur[d4.y], 1) : -1;
        int p2 = ((unsigned)d4.z < N_NODES) ? atomicAdd(&g_cur[d4.z], 1) : -1;
        int p3 = ((unsigned)d4.w < N_NODES) ? atomicAdd(&g_cur[d4.w], 1) : -1;
        if (p0 >= 0) g_csr[p0] = ((unsigned)s4.x < N_NODES) ? s4.x : 0;
        if (p1 >= 0) g_csr[p1] = ((unsigned)s4.y < N_NODES) ? s4.y : 0;
        if (p2 >= 0) g_csr[p2] = ((unsigned)s4.z < N_NODES) ? s4.z : 0;
        if (p3 >= 0) g_csr[p3] = ((unsigned)s4.w < N_NODES) ? s4.w : 0;
    }
}

// ---- packed f32x2 helpers (Blackwell FFMA2) ----

__device__ __forceinline__ unsigned long long pack2(float lo, float hi) {
    unsigned long long p;
    asm("mov.b64 %0, {%1, %2};" : "=l"(p) : "f"(lo), "f"(hi));
    return p;
}
__device__ __forceinline__ void unpack2(unsigned long long p, float& lo, float& hi) {
    asm("mov.b64 {%0, %1}, %2;" : "=f"(lo), "=f"(hi) : "l"(p));
}
__device__ __forceinline__ void ffma2(unsigned long long& d, unsigned long long a,
                                      unsigned long long b) {
    asm("fma.rn.f32x2 %0, %1, %2, %0;" : "+l"(d) : "l"(a), "l"(b));
}

// ------- GEMM 64x64 -> fp16 out, f32x2 packed FMA: out[n][j] = sum_k in[n][k]W[j][k]

__global__ __launch_bounds__(256) void k_gemm64h(const float* __restrict__ in,
                                                 const float* __restrict__ wt,
                                                 __half* __restrict__ out) {
    __shared__ __align__(16) float sW[64 * 64];
    __shared__ float sX[64 * 65];
    int n0 = blockIdx.x * 64;
    for (int i = threadIdx.x; i < 4096; i += 256) sW[i] = wt[i];
    for (int i = threadIdx.x; i < 4096; i += 256) {
        int n = i >> 6, k = i & 63;
        sX[n * 65 + k] = (n0 + n < N_NODES) ? in[(n0 + n) * 64 + k] : 0.f;
    }
    __syncthreads();
    int tx = threadIdx.x & 15, ty = threadIdx.x >> 4;
    unsigned long long accP[4][2] = {};
    #pragma unroll 8
    for (int k = 0; k < 64; k++) {
        double2 wd = *(const double2*)&sW[k * 64 + tx * 4];
        unsigned long long w01 = __double_as_longlong(wd.x);
        unsigned long long w23 = __double_as_longlong(wd.y);
        #pragma unroll
        for (int i = 0; i < 4; i++) {
            float xv = sX[(ty * 4 + i) * 65 + k];
            unsigned long long xp = pack2(xv, xv);
            ffma2(accP[i][0], xp, w01);
            ffma2(accP[i][1], xp, w23);
        }
    }
    #pragma unroll
    for (int i = 0; i < 4; i++) {
        int n = n0 + ty * 4 + i;
        if (n < N_NODES) {
            float a0, a1, a2, a3;
            unpack2(accP[i][0], a0, a1);
            unpack2(accP[i][1], a2, a3);
            __half2 h0 = __floats2half2_rn(a0, a1);
            __half2 h1 = __floats2half2_rn(a2, a3);
            uint2 pk = {*(unsigned*)&h0, *(unsigned*)&h1};
            *(uint2*)&out[n * 64 + tx * 4] = pk;
        }
    }
}

// ---- aggregation 64ch from fp16: warp per dst node, fp32 accum, no atomics ----

template <bool RELU>
__global__ __launch_bounds__(256) void k_agg64h(const __half2* __restrict__ h2,
                                                const float* __restrict__ bias,
                                                float* __restrict__ out) {
    int n = (blockIdx.x * blockDim.x + threadIdx.x) >> 5;
    int lane = threadIdx.x & 31;
    if (n >= N_NODES) return;
    int beg = g_off[n], end = g_off[n + 1];
    float ax = 0.f, ay = 0.f;
    int e = beg;
    for (; e + 4 <= end; e += 4) {
        int s0 = g_csr[e], s1 = g_csr[e + 1], s2 = g_csr[e + 2], s3 = g_csr[e + 3];
        float2 v0 = __half22float2(h2[s0 * 32 + lane]);
        float2 v1 = __half22float2(h2[s1 * 32 + lane]);
        float2 v2 = __half22float2(h2[s2 * 32 + lane]);
        float2 v3 = __half22float2(h2[s3 * 32 + lane]);
        ax += (v0.x + v1.x) + (v2.x + v3.x);
        ay += (v0.y + v1.y) + (v2.y + v3.y);
    }
    for (; e < end; e++) {
        float2 v = __half22float2(h2[g_csr[e] * 32 + lane]);
        ax += v.x; ay += v.y;
    }
    float2 b = ((const float2*)bias)[lane];
    float rx = ax + b.x, ry = ay + b.y;
    if (RELU) { rx = fmaxf(rx, 0.f); ry = fmaxf(ry, 0.f); }
    ((float2*)out)[n * 32 + lane] = make_float2(rx, ry);
}

// -------- layer 3 projection: 64 -> 7 (padded to 8), fp16 out --------

__global__ __launch_bounds__(128) void k_gemm7(const float* __restrict__ in) {
    __shared__ float sX[128 * 65];
    __shared__ float sW[64 * 8];
    int n0 = blockIdx.x * 128;
    for (int i = threadIdx.x; i < 512; i += 128) sW[i] = g_wt3[i];
    for (int i = threadIdx.x; i < 8192; i += 128) {
        int n = i >> 6, k = i & 63;
        sX[n * 65 + k] = (n0 + n < N_NODES) ? in[(n0 + n) * 64 + k] : 0.f;
    }
    __syncthreads();
    int n = n0 + threadIdx.x;
    float a[8] = {};
    #pragma unroll 8
    for (int k = 0; k < 64; k++) {
        float xv = sX[threadIdx.x * 65 + k];
        #pragma unroll
        for (int j = 0; j < 7; j++) a[j] += xv * sW[k * 8 + j];
    }
    if (n < N_NODES) {
        __half2 h0 = __floats2half2_rn(a[0], a[1]);
        __half2 h1 = __floats2half2_rn(a[2], a[3]);
        __half2 h2 = __floats2half2_rn(a[4], a[5]);
        __half2 h3 = __floats2half2_rn(a[6], 0.f);
        uint4 pk = {*(unsigned*)&h0, *(unsigned*)&h1, *(unsigned*)&h2, *(unsigned*)&h3};
        *(uint4*)&g_h3h[n * 8] = pk;
    }
}

// -------- aggregation 7ch (fp16 in) + bias + log_softmax, thread per node --------

__global__ __launch_bounds__(256) void k_agg7(const float* __restrict__ b3,
                                              float* __restrict__ out) {
    int n = blockIdx.x * blockDim.x + threadIdx.x;
    if (n >= N_NODES) return;
    int beg = g_off[n], end = g_off[n + 1];
    const uint4* __restrict__ p = (const uint4*)g_h3h;
    float a[7] = {};
    for (int e = beg; e < end; e++) {
        uint4 q = p[g_csr[e]];
        float2 f0 = __half22float2(*(__half2*)&q.x);
        float2 f1 = __half22float2(*(__half2*)&q.y);
        float2 f2 = __half22float2(*(__half2*)&q.z);
        float2 f3 = __half22float2(*(__half2*)&q.w);
        a[0] += f0.x; a[1] += f0.y; a[2] += f1.x; a[3] += f1.y;
        a[4] += f2.x; a[5] += f2.y; a[6] += f3.x;
    }
    #pragma unroll
    for (int j = 0; j < 7; j++) a[j] += b3[j];
    float m = a[0];
    #pragma unroll
    for (int j = 1; j < 7; j++) m = fmaxf(m, a[j]);
    float se = 0.f;
    #pragma unroll
    for (int j = 0; j < 7; j++) se += __expf(a[j] - m);
    float ls = __logf(se);
    #pragma unroll
    for (int j = 0; j < 7; j++) out[n * 7 + j] = a[j] - m - ls;
}

// ---------------- launch (fork/join: CSC chain overlaps gemm1) ----------------

static cudaStream_t g_s2 = nullptr;
static cudaEvent_t g_evF = nullptr, g_evJ = nullptr;

extern "C" void kernel_launch(void* const* d_in, const int* in_sizes, int n_in,
                              void* d_out, int out_size) {
    const float* x = (const float*)d_in[0];
    const int* ei = (const int*)d_in[1];
    const float* W1 = (const float*)d_in[2];
    const float* b1 = (const float*)d_in[3];
    const float* W2 = (const float*)d_in[4];
    const float* b2 = (const float*)d_in[5];
    const float* W3 = (const float*)d_in[6];
    const float* b3 = (const float*)d_in[7];
    float* out = (float*)d_out;

    if (!g_s2) {  // first call is the correctness run (pre-capture); handles persist
        cudaStreamCreateWithFlags(&g_s2, cudaStreamNonBlocking);
        cudaEventCreateWithFlags(&g_evF, cudaEventDisableTiming);
        cudaEventCreateWithFlags(&g_evJ, cudaEventDisableTiming);
    }

    void *pA, *pB, *pw1, *pw2;
    cudaGetSymbolAddress(&pA, g_hA);
    cudaGetSymbolAddress(&pB, g_bufB);
    cudaGetSymbolAddress(&pw1, g_wt1);
    cudaGetSymbolAddress(&pw2, g_wt2);

    // fork: CSC build on side stream
    cudaEventRecord(g_evF, 0);
    cudaStreamWaitEvent(g_s2, g_evF, 0);
    k_zero<<<(N_NODES + 255) / 256, 256, 0, g_s2>>>();
    k_hist<<<(N_EDGES / 4 + 255) / 256, 256, 0, g_s2>>>(ei);
    k_scan2<<<NB_SCAN, 1024, 0, g_s2>>>();
    k_scatter<<<(N_EDGES / 4 + 255) / 256, 256, 0, g_s2>>>(ei);
    cudaEventRecord(g_evJ, g_s2);

    // main stream: weight prep + layer-1 GEMM (independent of CSC)
    k_prep_w<<<1, 256>>>(W1, W2, W3);
    k_gemm64h<<<(N_NODES + 63) / 64, 256>>>(x, (const float*)pw1, (__half*)pA);

    // join
    cudaStreamWaitEvent(0, g_evJ, 0);

    k_agg64h<true><<<(N_NODES * 32 + 255) / 256, 256>>>((const __half2*)pA, b1, (float*)pB);
    k_gemm64h<<<(N_NODES + 63) / 64, 256>>>((const float*)pB, (const float*)pw2, (__half*)pA);
    k_agg64h<true><<<(N_NODES * 32 + 255) / 256, 256>>>((const __half2*)pA, b2, (float*)pB);
    k_gemm7<<<(N_NODES + 127) / 128, 128>>>((const float*)pB);
    k_agg7<<<(N_NODES + 255) / 256, 256>>>(b3, out);
}